// round 3
// baseline (speedup 1.0000x reference)
#include <cuda_runtime.h>
#include <math.h>

// SLIC superpixel k-means: 8 images of 224x224x3, K=100, 10 iterations + final assign.
// Output (float32): [labels (8*224*224)] ++ [mean_img (8*224*224*3)]

#define BATCH 8
#define H 224
#define W 224
#define HW (H * W)           // 50176
#define K 100
#define NITER 10
#define TPB 256
#define PPT 4                // pixels per thread
#define PPB (TPB * PPT)      // 1024
#define BLKS_PER_IMG (HW / PPB)  // 49 exactly

// Persistent scratch (device globals; no allocations allowed).
__device__ float g_centers[BATCH][K][5];
__device__ float g_accum[BATCH][K][6];   // 5 feature sums + count

__device__ __forceinline__ float slic_ratio() {
    // compactness / S, S = sqrt(H*W/K); computed in double then rounded to f32
    // (matches JAX: python float64 scalar weakly promoted into f32 ops)
    return (float)(10.0 / sqrt((double)HW / (double)K));
}

// --- init: centers on regular grid, zero accumulators ---
__global__ void slic_init_kernel(const float* __restrict__ img) {
    int b = blockIdx.x;
    int t = threadIdx.x;
    if (t < K) {
        int gi = t / 10, gj = t % 10;
        // floor((i+0.5)*H/g) in double — f32 would give 167 at i=7 (must be 168)
        int cy = (int)floor(((double)gi + 0.5) * (double)H / 10.0);
        int cx = (int)floor(((double)gj + 0.5) * (double)W / 10.0);
        int p = cy * W + cx;
        const float* px = img + ((size_t)b * HW + p) * 3;
        float ratio = slic_ratio();
        g_centers[b][t][0] = (float)cy * ratio;
        g_centers[b][t][1] = (float)cx * ratio;
        g_centers[b][t][2] = px[0];
        g_centers[b][t][3] = px[1];
        g_centers[b][t][4] = px[2];
    }
    float* acc = (float*)g_accum[b];
    for (int i = t; i < K * 6; i += blockDim.x) acc[i] = 0.0f;
}

// --- assign (+ accumulate, or + write final outputs) ---
template <int FINAL>
__global__ __launch_bounds__(TPB) void slic_assign_kernel(
    const float* __restrict__ img, float* __restrict__ out)
{
    __shared__ float s_c[K * 5];
    __shared__ float s_csq[K];
    __shared__ float s_acc[K * 6];

    const int b = blockIdx.y;
    const int t = threadIdx.x;

    const float* cbase = (const float*)g_centers[b];
    for (int i = t; i < K * 5; i += TPB) s_c[i] = cbase[i];
    if (!FINAL) {
        for (int i = t; i < K * 6; i += TPB) s_acc[i] = 0.0f;
    }
    __syncthreads();
    if (t < K) {
        float c0 = s_c[t * 5 + 0], c1 = s_c[t * 5 + 1], c2 = s_c[t * 5 + 2];
        float c3 = s_c[t * 5 + 3], c4 = s_c[t * 5 + 4];
        s_csq[t] = c0 * c0 + c1 * c1 + c2 * c2 + c3 * c3 + c4 * c4;
    }
    __syncthreads();

    const float ratio = slic_ratio();
    const int base = blockIdx.x * PPB + t * PPT;  // 4 consecutive pixels

    // coalesced vectorized load of 4 pixels (12 floats = 3x float4, 16B aligned:
    // offsets are multiples of 48B from a 16B-aligned base)
    const float4* p4 = (const float4*)(img + ((size_t)b * HW + (size_t)blockIdx.x * PPB) * 3);
    float4 v0 = p4[t * 3 + 0];
    float4 v1 = p4[t * 3 + 1];
    float4 v2 = p4[t * 3 + 2];
    float rr[4] = {v0.x, v0.w, v1.z, v2.y};
    float gg[4] = {v0.y, v1.x, v1.w, v2.z};
    float bb[4] = {v0.z, v1.y, v2.x, v2.w};

    float fy[4], fx[4], fsq[4], bd[4];
    int bestk[4];
#pragma unroll
    for (int j = 0; j < PPT; j++) {
        int p = base + j;
        int y = p / W;
        int x = p - y * W;
        fy[j] = (float)y * ratio;
        fx[j] = (float)x * ratio;
        fsq[j] = fy[j] * fy[j] + fx[j] * fx[j] + rr[j] * rr[j] + gg[j] * gg[j] + bb[j] * bb[j];
        bd[j] = 3.4e38f;
        bestk[j] = 0;
    }

    // nearest-center search; d = (f_sq + |c|^2) - 2*f.c  (reference formula),
    // strict '<' keeps the FIRST minimum (jnp.argmin tie-break)
#pragma unroll 2
    for (int k = 0; k < K; k++) {
        float c0 = s_c[k * 5 + 0], c1 = s_c[k * 5 + 1], c2 = s_c[k * 5 + 2];
        float c3 = s_c[k * 5 + 3], c4 = s_c[k * 5 + 4];
        float cs = s_csq[k];
#pragma unroll
        for (int j = 0; j < PPT; j++) {
            float dot = fy[j] * c0 + fx[j] * c1 + rr[j] * c2 + gg[j] * c3 + bb[j] * c4;
            float d = (fsq[j] + cs) - 2.0f * dot;
            if (d < bd[j]) { bd[j] = d; bestk[j] = k; }
        }
    }

    if (FINAL) {
        float* mean_out = out + (size_t)BATCH * HW;
#pragma unroll
        for (int j = 0; j < PPT; j++) {
            int p = base + j;
            int k = bestk[j];
            out[(size_t)b * HW + p] = (float)k;                     // labels as f32
            float* m = mean_out + ((size_t)b * HW + p) * 3;
            m[0] = s_c[k * 5 + 2];
            m[1] = s_c[k * 5 + 3];
            m[2] = s_c[k * 5 + 4];
        }
    } else {
        // run-length compressed accumulation (consecutive pixels usually share a label)
        int cur = bestk[0];
        float a0 = fy[0], a1 = fx[0], a2 = rr[0], a3 = gg[0], a4 = bb[0], cnt = 1.0f;
#pragma unroll
        for (int j = 1; j < PPT; j++) {
            if (bestk[j] == cur) {
                a0 += fy[j]; a1 += fx[j]; a2 += rr[j]; a3 += gg[j]; a4 += bb[j]; cnt += 1.0f;
            } else {
                atomicAdd(&s_acc[cur * 6 + 0], a0);
                atomicAdd(&s_acc[cur * 6 + 1], a1);
                atomicAdd(&s_acc[cur * 6 + 2], a2);
                atomicAdd(&s_acc[cur * 6 + 3], a3);
                atomicAdd(&s_acc[cur * 6 + 4], a4);
                atomicAdd(&s_acc[cur * 6 + 5], cnt);
                cur = bestk[j];
                a0 = fy[j]; a1 = fx[j]; a2 = rr[j]; a3 = gg[j]; a4 = bb[j]; cnt = 1.0f;
            }
        }
        atomicAdd(&s_acc[cur * 6 + 0], a0);
        atomicAdd(&s_acc[cur * 6 + 1], a1);
        atomicAdd(&s_acc[cur * 6 + 2], a2);
        atomicAdd(&s_acc[cur * 6 + 3], a3);
        atomicAdd(&s_acc[cur * 6 + 4], a4);
        atomicAdd(&s_acc[cur * 6 + 5], cnt);
        __syncthreads();

        float* gacc = (float*)g_accum[b];
        for (int i = t; i < K * 6; i += TPB) {
            float v = s_acc[i];
            if (v != 0.0f) atomicAdd(&gacc[i], v);
        }
    }
}

// --- center update: means of clusters; keep old center if empty; re-zero accum ---
__global__ void slic_update_kernel() {
    int b = blockIdx.x;
    int t = threadIdx.x;
    if (t < K) {
        float cnt = g_accum[b][t][5];
        if (cnt > 0.0f) {
            float den = fmaxf(cnt, 1.0f);
#pragma unroll
            for (int i = 0; i < 5; i++)
                g_centers[b][t][i] = g_accum[b][t][i] / den;  // IEEE div like jnp
        }
    }
    __syncthreads();
    float* acc = (float*)g_accum[b];
    for (int i = t; i < K * 6; i += blockDim.x) acc[i] = 0.0f;
}

extern "C" void kernel_launch(void* const* d_in, const int* in_sizes, int n_in,
                              void* d_out, int out_size)
{
    const float* img = (const float*)d_in[0];
    float* out = (float*)d_out;
    (void)in_sizes; (void)n_in; (void)out_size;

    slic_init_kernel<<<BATCH, 128>>>(img);

    dim3 grid(BLKS_PER_IMG, BATCH);
    for (int it = 0; it < NITER; ++it) {
        slic_assign_kernel<0><<<grid, TPB>>>(img, out);
        slic_update_kernel<<<BATCH, 128>>>();
    }
    slic_assign_kernel<1><<<grid, TPB>>>(img, out);
}